// round 9
// baseline (speedup 1.0000x reference)
#include <cuda_runtime.h>
#include <cuda_fp16.h>
#include <math.h>
#include <stdint.h>

// Shapes (fixed)
#define BB 128
#define SS 1024
#define DD 256
#define AA 256
#define OO 256
#define NROWS (BB*SS)
#define SPLITS 16

#define LDA 264            // xs row stride in halfs (132 words -> banks 4g+t, conflict-free)
#define LDK 24             // weight chunk row stride in halfs (12 words -> banks 12g+t, conflict-free)
#define CHUNK_B (256*LDK*2)   // 12288 bytes per 16-k weight chunk

// smem byte offsets
#define O_XS   0               // 128*264*2 = 67584
#define O_WB   67584           // 2*12288  = 24576
#define O_BS   92160           // 256 f32
#define O_US   93184           // 256 f32
#define O_MS   94208           // 128 f32
#define O_RED  94720           // 128*4 f32 = 2048
#define SMEM_BYTES 96768

// Scratch
__device__ float g_vu[NROWS];
__device__ float g_part[BB * SPLITS * OO];
__device__ __half g_Wh[DD * AA];    // W  transposed to [a][d], fp16
__device__ __half g_Uh[AA * OO];    // Uo transposed to [o][a], fp16

// ---------------------------------------------------------------------------
__device__ __forceinline__ uint32_t smem_u32(const void* p) {
    uint32_t a;
    asm("{ .reg .u64 t; cvta.to.shared.u64 t, %1; cvt.u32.u64 %0, t; }" : "=r"(a) : "l"(p));
    return a;
}
__device__ __forceinline__ void cp16(uint32_t dst, const void* src) {
    asm volatile("cp.async.cg.shared.global [%0], [%1], 16;" :: "r"(dst), "l"(src));
}
#define CP_COMMIT() asm volatile("cp.async.commit_group;" ::: "memory")
#define CP_WAIT0()  asm volatile("cp.async.wait_group 0;" ::: "memory")
#define CP_WAIT1()  asm volatile("cp.async.wait_group 1;" ::: "memory")

__device__ __forceinline__ void mma16(float* c, const uint32_t* a, uint32_t b0, uint32_t b1) {
    asm("mma.sync.aligned.m16n8k16.row.col.f32.f16.f16.f32 "
        "{%0,%1,%2,%3}, {%4,%5,%6,%7}, {%8,%9}, {%0,%1,%2,%3};"
        : "+f"(c[0]), "+f"(c[1]), "+f"(c[2]), "+f"(c[3])
        : "r"(a[0]), "r"(a[1]), "r"(a[2]), "r"(a[3]), "r"(b0), "r"(b1));
}

// issue one 16k x 256n fp16 chunk: 512 threads, 1 cp16 each
__device__ __forceinline__ void issue_chunk(uint32_t dst, const __half* gsrc, int tid) {
    int n = tid >> 1, p = tid & 1;
    cp16(dst + (uint32_t)(n * LDK * 2 + p * 16), gsrc + n * 256 + p * 8);
    CP_COMMIT();
}

// one 16-k step of MMAs for this warp's 32x64 tile
__device__ __forceinline__ void compute_chunk(float acc[2][8][4], const __half* xs,
                                              const __half* wbh, int kbase,
                                              int wr, int wc, int gid, int tig) {
    uint32_t a[2][4];
    #pragma unroll
    for (int mt = 0; mt < 2; mt++) {
        const __half* xr = xs + (wr*32 + mt*16 + gid) * LDA + kbase + 2*tig;
        a[mt][0] = *(const uint32_t*)xr;
        a[mt][1] = *(const uint32_t*)(xr + 8*LDA);
        a[mt][2] = *(const uint32_t*)(xr + 8);
        a[mt][3] = *(const uint32_t*)(xr + 8*LDA + 8);
    }
    #pragma unroll
    for (int nt = 0; nt < 8; nt++) {
        const __half* wp = wbh + (wc*64 + nt*8 + gid) * LDK + 2*tig;
        uint32_t b0 = *(const uint32_t*)wp;
        uint32_t b1 = *(const uint32_t*)(wp + 8);
        mma16(acc[0][nt], a[0], b0, b1);
        mma16(acc[1][nt], a[1], b0, b1);
    }
}

// 16 chunks, double-buffered; chunks 0,1 pre-issued and chunk0 visible
__device__ __forceinline__ void gemm_loop(float acc[2][8][4], const __half* __restrict__ gW,
                                          const __half* xs, const __half* wbh, uint32_t wb_u32,
                                          int wr, int wc, int gid, int tig, int tid) {
    for (int kc = 0; kc < 16; kc++) {
        const int cur = kc & 1;
        compute_chunk(acc, xs, wbh + cur * (CHUNK_B/2), kc * 16, wr, wc, gid, tig);
        __syncthreads();
        if (kc + 2 < 16)
            issue_chunk(wb_u32 + (uint32_t)cur * CHUNK_B, gW + (kc + 2) * 16, tid);
        if (kc + 1 < 16) {
            if (kc + 2 < 16) CP_WAIT1(); else CP_WAIT0();
            __syncthreads();
        }
    }
}

// ---------------------------------------------------------------------------
// Transpose + fp16 convert: g_Wh[a][d] = W[d][a], g_Uh[o][a] = Uo[a][o]
// ---------------------------------------------------------------------------
__global__ void k_prep(const float* __restrict__ W, const float* __restrict__ Uo)
{
    __shared__ float t[32][33];
    const float* src = blockIdx.z ? Uo : W;
    __half* dst = blockIdx.z ? g_Uh : g_Wh;
    int x0 = blockIdx.x * 32, y0 = blockIdx.y * 32;
    #pragma unroll
    for (int i = 0; i < 32; i += 8)
        t[threadIdx.y + i][threadIdx.x] = src[(y0 + threadIdx.y + i) * 256 + x0 + threadIdx.x];
    __syncthreads();
    #pragma unroll
    for (int i = 0; i < 32; i += 8)
        dst[(x0 + threadIdx.y + i) * 256 + y0 + threadIdx.x] = __float2half_rn(t[threadIdx.x][threadIdx.y + i]);
}

// ---------------------------------------------------------------------------
// Fused kernel: 128-row tile, 512 threads, fp16 MMA, register epilogues
// ---------------------------------------------------------------------------
__global__ void __launch_bounds__(512, 2)
k_fused(const float* __restrict__ x, const float* __restrict__ mask,
        const float* __restrict__ bvec, const float* __restrict__ u,
        float* __restrict__ betas_out)
{
    extern __shared__ char smc[];
    __half* xs  = (__half*)(smc + O_XS);
    __half* wbh = (__half*)(smc + O_WB);
    float* bs   = (float*)(smc + O_BS);
    float* us   = (float*)(smc + O_US);
    float* ms   = (float*)(smc + O_MS);
    float* red  = (float*)(smc + O_RED);     // [128][4]

    const uint32_t smb    = smem_u32(smc);
    const uint32_t wb_u32 = smb + O_WB;

    const int tid  = threadIdx.x;
    const int lane = tid & 31;
    const int wid  = tid >> 5;
    const int wr   = wid >> 2;       // 0..3: 32-row stripe
    const int wc   = wid & 3;        // 0..3: 64-col quarter
    const int gid  = lane >> 2;
    const int tig  = lane & 3;
    const int row0 = blockIdx.x * 128;

    // headers
    if (tid < 256) { bs[tid] = bvec[tid]; us[tid] = u[tid]; }
    if (tid < 128) ms[tid] = mask[row0 + tid];

    // async-prefetch W chunks 0,1; then convert x tile to fp16 smem
    issue_chunk(wb_u32, g_Wh, tid);
    issue_chunk(wb_u32 + CHUNK_B, g_Wh + 16, tid);
    {
        const float* xg = x + (size_t)row0 * DD;
        #pragma unroll
        for (int i = 0; i < 16; i++) {
            int idx = tid + i * 512;             // 8192 float4s
            int row = idx >> 6, c4 = (idx & 63) * 4;
            float4 v = *(const float4*)(xg + row * 256 + c4);
            __half2 h0 = __floats2half2_rn(v.x, v.y);
            __half2 h1 = __floats2half2_rn(v.z, v.w);
            *(__half2*)(xs + row * LDA + c4)     = h0;
            *(__half2*)(xs + row * LDA + c4 + 2) = h1;
        }
    }
    CP_WAIT1();
    __syncthreads();

    float acc[2][8][4];

    // ---------------- GEMM1: t = x @ W ----------------
    #pragma unroll
    for (int mt = 0; mt < 2; mt++)
        #pragma unroll
        for (int nt = 0; nt < 8; nt++)
            #pragma unroll
            for (int c = 0; c < 4; c++) acc[mt][nt][c] = 0.0f;

    gemm_loop(acc, g_Wh, xs, wbh, wb_u32, wr, wc, gid, tig, tid);

    // prefetch Uo chunks 0,1 during epilogue1
    issue_chunk(wb_u32, g_Uh, tid);
    issue_chunk(wb_u32 + CHUNK_B, g_Uh + 16, tid);

    // ---------------- epilogue1 (registers): bias + normalize + tanh + vu; v->xs fp16
    {
        // rows held by this thread: r[mt][rh] = wr*32 + mt*16 + rh*8 + gid
        float ss[2][2] = {{0,0},{0,0}};
        #pragma unroll
        for (int mt = 0; mt < 2; mt++)
            #pragma unroll
            for (int nt = 0; nt < 8; nt++)
                #pragma unroll
                for (int c = 0; c < 4; c++) {
                    int col = wc*64 + nt*8 + 2*tig + (c & 1);
                    float t = acc[mt][nt][c] + bs[col];
                    acc[mt][nt][c] = t;
                    ss[mt][c>>1] = fmaf(t, t, ss[mt][c>>1]);
                }
        #pragma unroll
        for (int mt = 0; mt < 2; mt++)
            #pragma unroll
            for (int rh = 0; rh < 2; rh++) {
                ss[mt][rh] += __shfl_xor_sync(0xffffffffu, ss[mt][rh], 1);
                ss[mt][rh] += __shfl_xor_sync(0xffffffffu, ss[mt][rh], 2);
            }
        if (tig == 0) {
            #pragma unroll
            for (int mt = 0; mt < 2; mt++)
                #pragma unroll
                for (int rh = 0; rh < 2; rh++)
                    red[(wr*32 + mt*16 + rh*8 + gid)*4 + wc] = ss[mt][rh];
        }
        __syncthreads();
        float invn[2][2];
        #pragma unroll
        for (int mt = 0; mt < 2; mt++)
            #pragma unroll
            for (int rh = 0; rh < 2; rh++) {
                int r = wr*32 + mt*16 + rh*8 + gid;
                float s = red[r*4+0] + red[r*4+1] + red[r*4+2] + red[r*4+3];
                invn[mt][rh] = 1.0f / fmaxf(sqrtf(s), 1e-12f);
            }
        __syncthreads();                     // red free for reuse
        float vu[2][2] = {{0,0},{0,0}};
        #pragma unroll
        for (int mt = 0; mt < 2; mt++)
            #pragma unroll
            for (int nt = 0; nt < 8; nt++) {
                #pragma unroll
                for (int c = 0; c < 4; c++) {
                    int col = wc*64 + nt*8 + 2*tig + (c & 1);
                    float a = acc[mt][nt][c] * invn[mt][c>>1];   // |a| <= 1
                    float e = __expf(2.0f * a);
                    float v = __fdividef(e - 1.0f, e + 1.0f);
                    acc[mt][nt][c] = v;
                    vu[mt][c>>1] = fmaf(v, us[col], vu[mt][c>>1]);
                }
                // store v pairs to xs (fp16) for GEMM2 A operand
                int cb = wc*64 + nt*8 + 2*tig;
                int r0 = wr*32 + mt*16 + gid;
                *(__half2*)(xs + r0*LDA + cb)       = __floats2half2_rn(acc[mt][nt][0], acc[mt][nt][1]);
                *(__half2*)(xs + (r0+8)*LDA + cb)   = __floats2half2_rn(acc[mt][nt][2], acc[mt][nt][3]);
            }
        #pragma unroll
        for (int mt = 0; mt < 2; mt++)
            #pragma unroll
            for (int rh = 0; rh < 2; rh++) {
                vu[mt][rh] += __shfl_xor_sync(0xffffffffu, vu[mt][rh], 1);
                vu[mt][rh] += __shfl_xor_sync(0xffffffffu, vu[mt][rh], 2);
            }
        if (tig == 0) {
            #pragma unroll
            for (int mt = 0; mt < 2; mt++)
                #pragma unroll
                for (int rh = 0; rh < 2; rh++)
                    red[(wr*32 + mt*16 + rh*8 + gid)*4 + wc] = vu[mt][rh];
        }
        __syncthreads();
        if (wc == 0 && tig == 0) {
            #pragma unroll
            for (int mt = 0; mt < 2; mt++)
                #pragma unroll
                for (int rh = 0; rh < 2; rh++) {
                    int r = wr*32 + mt*16 + rh*8 + gid;
                    float s = red[r*4+0] + red[r*4+1] + red[r*4+2] + red[r*4+3];
                    g_vu[row0 + r] = s * ms[r];
                }
        }
    }
    CP_WAIT1();
    __syncthreads();                          // Uo chunk0 + v tile visible

    // ---------------- GEMM2: vuo = v @ Uo ----------------
    #pragma unroll
    for (int mt = 0; mt < 2; mt++)
        #pragma unroll
        for (int nt = 0; nt < 8; nt++)
            #pragma unroll
            for (int c = 0; c < 4; c++) acc[mt][nt][c] = 0.0f;

    gemm_loop(acc, g_Uh, xs, wbh, wb_u32, wr, wc, gid, tig, tid);

    // ---------------- epilogue2 (registers): mask + softmax over O -> betas
    {
        float mx[2][2] = {{-3.4e38f,-3.4e38f},{-3.4e38f,-3.4e38f}};
        #pragma unroll
        for (int mt = 0; mt < 2; mt++)
            #pragma unroll
            for (int nt = 0; nt < 8; nt++)
                #pragma unroll
                for (int c = 0; c < 4; c++) {
                    int r = wr*32 + mt*16 + ((c>>1)*8) + gid;
                    float v = acc[mt][nt][c] * ms[r];
                    acc[mt][nt][c] = v;
                    mx[mt][c>>1] = fmaxf(mx[mt][c>>1], v);
                }
        #pragma unroll
        for (int mt = 0; mt < 2; mt++)
            #pragma unroll
            for (int rh = 0; rh < 2; rh++) {
                mx[mt][rh] = fmaxf(mx[mt][rh], __shfl_xor_sync(0xffffffffu, mx[mt][rh], 1));
                mx[mt][rh] = fmaxf(mx[mt][rh], __shfl_xor_sync(0xffffffffu, mx[mt][rh], 2));
            }
        if (tig == 0) {
            #pragma unroll
            for (int mt = 0; mt < 2; mt++)
                #pragma unroll
                for (int rh = 0; rh < 2; rh++)
                    red[(wr*32 + mt*16 + rh*8 + gid)*4 + wc] = mx[mt][rh];
        }
        __syncthreads();
        float mxf[2][2];
        #pragma unroll
        for (int mt = 0; mt < 2; mt++)
            #pragma unroll
            for (int rh = 0; rh < 2; rh++) {
                int r = wr*32 + mt*16 + rh*8 + gid;
                mxf[mt][rh] = fmaxf(fmaxf(red[r*4+0], red[r*4+1]), fmaxf(red[r*4+2], red[r*4+3]));
            }
        __syncthreads();
        float sume[2][2] = {{0,0},{0,0}};
        #pragma unroll
        for (int mt = 0; mt < 2; mt++)
            #pragma unroll
            for (int nt = 0; nt < 8; nt++)
                #pragma unroll
                for (int c = 0; c < 4; c++) {
                    int r = wr*32 + mt*16 + ((c>>1)*8) + gid;
                    float e = __expf(acc[mt][nt][c] - mxf[mt][c>>1]) * ms[r];
                    acc[mt][nt][c] = e;
                    sume[mt][c>>1] += e;
                }
        #pragma unroll
        for (int mt = 0; mt < 2; mt++)
            #pragma unroll
            for (int rh = 0; rh < 2; rh++) {
                sume[mt][rh] += __shfl_xor_sync(0xffffffffu, sume[mt][rh], 1);
                sume[mt][rh] += __shfl_xor_sync(0xffffffffu, sume[mt][rh], 2);
            }
        if (tig == 0) {
            #pragma unroll
            for (int mt = 0; mt < 2; mt++)
                #pragma unroll
                for (int rh = 0; rh < 2; rh++)
                    red[(wr*32 + mt*16 + rh*8 + gid)*4 + wc] = sume[mt][rh];
        }
        __syncthreads();
        float* bo = betas_out + (size_t)row0 * OO;
        #pragma unroll
        for (int mt = 0; mt < 2; mt++) {
            float inv[2];
            #pragma unroll
            for (int rh = 0; rh < 2; rh++) {
                int r = wr*32 + mt*16 + rh*8 + gid;
                float s = red[r*4+0] + red[r*4+1] + red[r*4+2] + red[r*4+3];
                inv[rh] = (s == 0.0f) ? 1.0f : __fdividef(1.0f, s);
            }
            int r0 = wr*32 + mt*16 + gid;
            #pragma unroll
            for (int nt = 0; nt < 8; nt++) {
                int cb = wc*64 + nt*8 + 2*tig;
                *(float2*)(bo + (size_t)r0 * OO + cb)       = make_float2(acc[mt][nt][0]*inv[0], acc[mt][nt][1]*inv[0]);
                *(float2*)(bo + (size_t)(r0+8) * OO + cb)   = make_float2(acc[mt][nt][2]*inv[1], acc[mt][nt][3]*inv[1]);
            }
        }
    }
}

// ---------------------------------------------------------------------------
// alphas = masked softmax of g_vu over S, per batch
// ---------------------------------------------------------------------------
__global__ __launch_bounds__(1024)
void k_alphas(const float* __restrict__ mask, float* __restrict__ alphas)
{
    __shared__ float redA[32];
    __shared__ float redB[32];
    const int b = blockIdx.x;
    const int s = threadIdx.x;
    const int lane = s & 31, wid = s >> 5;

    float val = g_vu[b*SS + s];
    float m   = mask[b*SS + s];

    float wm = val;
    #pragma unroll
    for (int off = 16; off; off >>= 1) wm = fmaxf(wm, __shfl_xor_sync(0xffffffffu, wm, off));
    if (lane == 0) redA[wid] = wm;
    __syncthreads();
    if (wid == 0) {
        float t = redA[lane];
        #pragma unroll
        for (int off = 16; off; off >>= 1) t = fmaxf(t, __shfl_xor_sync(0xffffffffu, t, off));
        if (lane == 0) redA[0] = t;
    }
    __syncthreads();
    float mx = redA[0];

    float e = __expf(val - mx) * m;
    float wsm = e;
    #pragma unroll
    for (int off = 16; off; off >>= 1) wsm += __shfl_xor_sync(0xffffffffu, wsm, off);
    if (lane == 0) redB[wid] = wsm;
    __syncthreads();
    if (wid == 0) {
        float t = redB[lane];
        #pragma unroll
        for (int off = 16; off; off >>= 1) t += __shfl_xor_sync(0xffffffffu, t, off);
        if (lane == 0) redB[0] = t;
    }
    __syncthreads();
    float sum = redB[0];
    float inv = (sum == 0.0f) ? 1.0f : (1.0f / sum);
    alphas[b*SS + s] = e * inv;
}

// ---------------------------------------------------------------------------
// output partials over 64-row S-splits + deterministic reduce
// ---------------------------------------------------------------------------
__global__ __launch_bounds__(256)
void k_partial(const float* __restrict__ x, const float* __restrict__ alphas,
               const float* __restrict__ betas)
{
    __shared__ float as[64];
    __shared__ float4 red[4][64];
    const int b = blockIdx.x, sp = blockIdx.y;
    const int tid = threadIdx.x;
    const int o4 = tid & 63, sq = tid >> 6;
    const int s0 = sp * 64;

    if (tid < 64) as[tid] = alphas[b*SS + s0 + tid];
    __syncthreads();

    float4 acc = make_float4(0.f, 0.f, 0.f, 0.f);
    #pragma unroll 4
    for (int si = sq; si < 64; si += 4) {
        float a = as[si];
        if (a != 0.0f) {
            size_t base = ((size_t)b * SS + s0 + si) * OO + o4 * 4;
            float4 xv = *(const float4*)(x + base);
            float4 bv = *(const float4*)(betas + base);
            acc.x = fmaf(xv.x * a, bv.x, acc.x);
            acc.y = fmaf(xv.y * a, bv.y, acc.y);
            acc.z = fmaf(xv.z * a, bv.z, acc.z);
            acc.w = fmaf(xv.w * a, bv.w, acc.w);
        }
    }
    red[sq][o4] = acc;
    __syncthreads();
    if (tid < 64) {
        float4 r0 = red[0][tid], r1 = red[1][tid], r2 = red[2][tid], r3 = red[3][tid];
        float4 s = make_float4(r0.x + r1.x + r2.x + r3.x,
                               r0.y + r1.y + r2.y + r3.y,
                               r0.z + r1.z + r2.z + r3.z,
                               r0.w + r1.w + r2.w + r3.w);
        *(float4*)&g_part[((size_t)b * SPLITS + sp) * OO + tid * 4] = s;
    }
}

__global__ __launch_bounds__(256)
void k_reduce(float* __restrict__ out)
{
    const int idx = blockIdx.x * 256 + threadIdx.x;
    const int b = idx >> 8, o = idx & 255;
    float s = 0.0f;
    #pragma unroll
    for (int sp = 0; sp < SPLITS; sp++) s += g_part[((size_t)b * SPLITS + sp) * OO + o];
    out[idx] = s;
}

// ---------------------------------------------------------------------------
extern "C" void kernel_launch(void* const* d_in, const int* in_sizes, int n_in,
                              void* d_out, int out_size)
{
    const float* x    = (const float*)d_in[0];   // [B,S,D]
    const float* mask = (const float*)d_in[1];   // [B,S]
    const float* W    = (const float*)d_in[2];   // [D,A]
    const float* bv   = (const float*)d_in[3];   // [A]
    const float* u    = (const float*)d_in[4];   // [A]
    const float* Uo   = (const float*)d_in[5];   // [A,O]

    float* out    = (float*)d_out;               // [B,O]
    float* alphas = out + BB * OO;               // [B,S]
    float* betas  = alphas + BB * SS;            // [B,S,O]

    cudaFuncSetAttribute(k_fused, cudaFuncAttributeMaxDynamicSharedMemorySize, SMEM_BYTES);

    dim3 tg(8, 8, 2), tb(32, 8);
    k_prep<<<tg, tb>>>(W, Uo);
    k_fused<<<NROWS / 128, 512, SMEM_BYTES>>>(x, mask, bv, u, betas);
    k_alphas<<<BB, 1024>>>(mask, alphas);
    dim3 g3(BB, SPLITS);
    k_partial<<<g3, 256>>>(x, alphas, betas);
    k_reduce<<<(BB * OO) / 256, 256>>>(out);
}

// round 10
// speedup vs baseline: 2.8195x; 2.8195x over previous
#include <cuda_runtime.h>
#include <cuda_fp16.h>
#include <math.h>
#include <stdint.h>

// Shapes (fixed)
#define BB 128
#define SS 1024
#define DD 256
#define AA 256
#define OO 256
#define NROWS (BB*SS)
#define SPLITS 16

#define TILE_R 64
#define LDA 264            // xs row stride in halfs -> banks 4*gid+tig, conflict-free
#define LDK 40             // weight row stride in halfs (32 payload + 8 pad) -> banks 20*gid+tig
#define CHUNK_B (256*LDK*2)   // 20480 bytes per 32-k weight chunk

// smem byte offsets
#define O_XS   0               // 64*264*2 = 33792
#define O_WB   33792           // 2*20480 = 40960
#define O_BS   74752           // 256 f32
#define O_US   75776           // 256 f32
#define O_MS   76800           // 64 f32
#define O_RED  77056           // 64*4 f32
#define SMEM_BYTES 78080

// Scratch
__device__ float g_vu[NROWS];
__device__ float g_part[BB * SPLITS * OO];
__device__ __half g_Wh[DD * AA];    // W  transposed to [a][d], fp16
__device__ __half g_Uh[AA * OO];    // Uo transposed to [o][a], fp16

// ---------------------------------------------------------------------------
__device__ __forceinline__ uint32_t smem_u32(const void* p) {
    uint32_t a;
    asm("{ .reg .u64 t; cvta.to.shared.u64 t, %1; cvt.u32.u64 %0, t; }" : "=r"(a) : "l"(p));
    return a;
}
__device__ __forceinline__ void cp16(uint32_t dst, const void* src) {
    asm volatile("cp.async.cg.shared.global [%0], [%1], 16;" :: "r"(dst), "l"(src));
}
#define CP_COMMIT() asm volatile("cp.async.commit_group;" ::: "memory")
#define CP_WAIT0()  asm volatile("cp.async.wait_group 0;" ::: "memory")
#define CP_WAIT1()  asm volatile("cp.async.wait_group 1;" ::: "memory")

__device__ __forceinline__ void mma16(float* c, const uint32_t* a, uint32_t b0, uint32_t b1) {
    asm("mma.sync.aligned.m16n8k16.row.col.f32.f16.f16.f32 "
        "{%0,%1,%2,%3}, {%4,%5,%6,%7}, {%8,%9}, {%0,%1,%2,%3};"
        : "+f"(c[0]), "+f"(c[1]), "+f"(c[2]), "+f"(c[3])
        : "r"(a[0]), "r"(a[1]), "r"(a[2]), "r"(a[3]), "r"(b0), "r"(b1));
}

// issue one 32k x 256n fp16 chunk: 256 threads, 4 cp16 each; gsrc = row0 of [n][256] + koff
__device__ __forceinline__ void issue_chunk(uint32_t dst, const __half* gsrc, int tid) {
    const __half* s = gsrc + tid * 256;
    uint32_t d = dst + (uint32_t)(tid * LDK * 2);
    #pragma unroll
    for (int p = 0; p < 4; p++) cp16(d + p * 16, s + p * 8);
    CP_COMMIT();
}

// one 32-k chunk of MMAs for this warp's 32x64 tile (two 16-k steps)
__device__ __forceinline__ void compute_chunk(float acc[2][8][4], const __half* xs,
                                              const __half* wbh, int kbase,
                                              int wr, int wc, int gid, int tig) {
    #pragma unroll
    for (int ks = 0; ks < 2; ks++) {
        const int ko = kbase + ks * 16;
        uint32_t a[2][4];
        #pragma unroll
        for (int mt = 0; mt < 2; mt++) {
            const __half* xr = xs + (wr*32 + mt*16 + gid) * LDA + ko + 2*tig;
            a[mt][0] = *(const uint32_t*)xr;
            a[mt][1] = *(const uint32_t*)(xr + 8*LDA);
            a[mt][2] = *(const uint32_t*)(xr + 8);
            a[mt][3] = *(const uint32_t*)(xr + 8*LDA + 8);
        }
        #pragma unroll
        for (int nt = 0; nt < 8; nt++) {
            const __half* wp = wbh + (wc*64 + nt*8 + gid) * LDK + ks*16 + 2*tig;
            uint32_t b0 = *(const uint32_t*)wp;
            uint32_t b1 = *(const uint32_t*)(wp + 8);
            mma16(acc[0][nt], a[0], b0, b1);
            mma16(acc[1][nt], a[1], b0, b1);
        }
    }
}

// 8 chunks, double-buffered; chunks 0,1 pre-issued and chunk0 visible
__device__ __forceinline__ void gemm_loop(float acc[2][8][4], const __half* __restrict__ gW,
                                          const __half* xs, const __half* wbh, uint32_t wb_u32,
                                          int wr, int wc, int gid, int tig, int tid) {
    for (int kc = 0; kc < 8; kc++) {
        const int cur = kc & 1;
        compute_chunk(acc, xs, wbh + cur * (CHUNK_B/2), kc * 32, wr, wc, gid, tig);
        __syncthreads();
        if (kc + 2 < 8)
            issue_chunk(wb_u32 + (uint32_t)cur * CHUNK_B, gW + (kc + 2) * 32, tid);
        if (kc + 1 < 8) {
            if (kc + 2 < 8) CP_WAIT1(); else CP_WAIT0();
            __syncthreads();
        }
    }
}

// ---------------------------------------------------------------------------
// Transpose + fp16 convert: g_Wh[a][d] = W[d][a], g_Uh[o][a] = Uo[a][o]
// ---------------------------------------------------------------------------
__global__ void k_prep(const float* __restrict__ W, const float* __restrict__ Uo)
{
    __shared__ float t[32][33];
    const float* src = blockIdx.z ? Uo : W;
    __half* dst = blockIdx.z ? g_Uh : g_Wh;
    int x0 = blockIdx.x * 32, y0 = blockIdx.y * 32;
    #pragma unroll
    for (int i = 0; i < 32; i += 8)
        t[threadIdx.y + i][threadIdx.x] = src[(y0 + threadIdx.y + i) * 256 + x0 + threadIdx.x];
    __syncthreads();
    #pragma unroll
    for (int i = 0; i < 32; i += 8)
        dst[(x0 + threadIdx.y + i) * 256 + y0 + threadIdx.x] = __float2half_rn(t[threadIdx.x][threadIdx.y + i]);
}

// ---------------------------------------------------------------------------
// Fused kernel: 64-row tile, 256 threads, fp16 MMA, register epilogues, occ 2
// ---------------------------------------------------------------------------
__global__ void __launch_bounds__(256, 2)
k_fused(const float* __restrict__ x, const float* __restrict__ mask,
        const float* __restrict__ bvec, const float* __restrict__ u,
        float* __restrict__ betas_out)
{
    extern __shared__ char smc[];
    __half* xs  = (__half*)(smc + O_XS);
    __half* wbh = (__half*)(smc + O_WB);
    float* bs   = (float*)(smc + O_BS);
    float* us   = (float*)(smc + O_US);
    float* ms   = (float*)(smc + O_MS);
    float* red  = (float*)(smc + O_RED);     // [64][4]

    const uint32_t smb    = smem_u32(smc);
    const uint32_t wb_u32 = smb + O_WB;

    const int tid  = threadIdx.x;
    const int lane = tid & 31;
    const int wid  = tid >> 5;
    const int wr   = wid >> 2;       // 0..1: 32-row stripe
    const int wc   = wid & 3;        // 0..3: 64-col quarter
    const int gid  = lane >> 2;
    const int tig  = lane & 3;
    const int row0 = blockIdx.x * TILE_R;

    // headers
    bs[tid] = bvec[tid];
    us[tid] = u[tid];
    if (tid < TILE_R) ms[tid] = mask[row0 + tid];

    // async-prefetch W chunks 0,1; then convert x tile to fp16 smem
    issue_chunk(wb_u32, g_Wh, tid);
    issue_chunk(wb_u32 + CHUNK_B, g_Wh + 32, tid);
    {
        const float* xg = x + (size_t)row0 * DD;
        #pragma unroll
        for (int i = 0; i < 16; i++) {
            int idx = tid + i * 256;             // 4096 float4s
            int row = idx >> 6, c4 = (idx & 63) * 4;
            float4 v = *(const float4*)(xg + row * 256 + c4);
            *(__half2*)(xs + row * LDA + c4)     = __floats2half2_rn(v.x, v.y);
            *(__half2*)(xs + row * LDA + c4 + 2) = __floats2half2_rn(v.z, v.w);
        }
    }
    CP_WAIT1();
    __syncthreads();

    float acc[2][8][4];

    // ---------------- GEMM1: t = x @ W ----------------
    #pragma unroll
    for (int mt = 0; mt < 2; mt++)
        #pragma unroll
        for (int nt = 0; nt < 8; nt++)
            #pragma unroll
            for (int c = 0; c < 4; c++) acc[mt][nt][c] = 0.0f;

    gemm_loop(acc, g_Wh, xs, wbh, wb_u32, wr, wc, gid, tig, tid);

    // prefetch Uo chunks 0,1 during epilogue1
    issue_chunk(wb_u32, g_Uh, tid);
    issue_chunk(wb_u32 + CHUNK_B, g_Uh + 32, tid);

    // ---------------- epilogue1 (registers): bias + normalize + tanh + vu; v->xs fp16
    {
        float ss[2][2] = {{0,0},{0,0}};
        #pragma unroll
        for (int mt = 0; mt < 2; mt++)
            #pragma unroll
            for (int nt = 0; nt < 8; nt++)
                #pragma unroll
                for (int c = 0; c < 4; c++) {
                    int col = wc*64 + nt*8 + 2*tig + (c & 1);
                    float t = acc[mt][nt][c] + bs[col];
                    acc[mt][nt][c] = t;
                    ss[mt][c>>1] = fmaf(t, t, ss[mt][c>>1]);
                }
        #pragma unroll
        for (int mt = 0; mt < 2; mt++)
            #pragma unroll
            for (int rh = 0; rh < 2; rh++) {
                ss[mt][rh] += __shfl_xor_sync(0xffffffffu, ss[mt][rh], 1);
                ss[mt][rh] += __shfl_xor_sync(0xffffffffu, ss[mt][rh], 2);
            }
        if (tig == 0) {
            #pragma unroll
            for (int mt = 0; mt < 2; mt++)
                #pragma unroll
                for (int rh = 0; rh < 2; rh++)
                    red[(wr*32 + mt*16 + rh*8 + gid)*4 + wc] = ss[mt][rh];
        }
        __syncthreads();
        float invn[2][2];
        #pragma unroll
        for (int mt = 0; mt < 2; mt++)
            #pragma unroll
            for (int rh = 0; rh < 2; rh++) {
                int r = wr*32 + mt*16 + rh*8 + gid;
                float s = red[r*4+0] + red[r*4+1] + red[r*4+2] + red[r*4+3];
                invn[mt][rh] = 1.0f / fmaxf(sqrtf(s), 1e-12f);
            }
        __syncthreads();                     // red free for reuse
        float vu[2][2] = {{0,0},{0,0}};
        #pragma unroll
        for (int mt = 0; mt < 2; mt++)
            #pragma unroll
            for (int nt = 0; nt < 8; nt++) {
                #pragma unroll
                for (int c = 0; c < 4; c++) {
                    int col = wc*64 + nt*8 + 2*tig + (c & 1);
                    float a = acc[mt][nt][c] * invn[mt][c>>1];   // |a| <= 1
                    float e = __expf(2.0f * a);
                    float v = __fdividef(e - 1.0f, e + 1.0f);
                    acc[mt][nt][c] = v;
                    vu[mt][c>>1] = fmaf(v, us[col], vu[mt][c>>1]);
                }
                int cb = wc*64 + nt*8 + 2*tig;
                int r0 = wr*32 + mt*16 + gid;
                *(__half2*)(xs + r0*LDA + cb)     = __floats2half2_rn(acc[mt][nt][0], acc[mt][nt][1]);
                *(__half2*)(xs + (r0+8)*LDA + cb) = __floats2half2_rn(acc[mt][nt][2], acc[mt][nt][3]);
            }
        #pragma unroll
        for (int mt = 0; mt < 2; mt++)
            #pragma unroll
            for (int rh = 0; rh < 2; rh++) {
                vu[mt][rh] += __shfl_xor_sync(0xffffffffu, vu[mt][rh], 1);
                vu[mt][rh] += __shfl_xor_sync(0xffffffffu, vu[mt][rh], 2);
            }
        if (tig == 0) {
            #pragma unroll
            for (int mt = 0; mt < 2; mt++)
                #pragma unroll
                for (int rh = 0; rh < 2; rh++)
                    red[(wr*32 + mt*16 + rh*8 + gid)*4 + wc] = vu[mt][rh];
        }
        __syncthreads();
        if (wc == 0 && tig == 0) {
            #pragma unroll
            for (int mt = 0; mt < 2; mt++)
                #pragma unroll
                for (int rh = 0; rh < 2; rh++) {
                    int r = wr*32 + mt*16 + rh*8 + gid;
                    float s = red[r*4+0] + red[r*4+1] + red[r*4+2] + red[r*4+3];
                    g_vu[row0 + r] = s * ms[r];
                }
        }
    }
    CP_WAIT1();
    __syncthreads();                          // Uo chunk0 + v tile visible

    // ---------------- GEMM2: vuo = v @ Uo ----------------
    #pragma unroll
    for (int mt = 0; mt < 2; mt++)
        #pragma unroll
        for (int nt = 0; nt < 8; nt++)
            #pragma unroll
            for (int c = 0; c < 4; c++) acc[mt][nt][c] = 0.0f;

    gemm_loop(acc, g_Uh, xs, wbh, wb_u32, wr, wc, gid, tig, tid);

    // ---------------- epilogue2 (registers): mask + softmax over O -> betas
    {
        float mx[2][2] = {{-3.4e38f,-3.4e38f},{-3.4e38f,-3.4e38f}};
        #pragma unroll
        for (int mt = 0; mt < 2; mt++)
            #pragma unroll
            for (int nt = 0; nt < 8; nt++)
                #pragma unroll
                for (int c = 0; c < 4; c++) {
                    int r = wr*32 + mt*16 + ((c>>1)*8) + gid;
                    float v = acc[mt][nt][c] * ms[r];
                    acc[mt][nt][c] = v;
                    mx[mt][c>>1] = fmaxf(mx[mt][c>>1], v);
                }
        #pragma unroll
        for (int mt = 0; mt < 2; mt++)
            #pragma unroll
            for (int rh = 0; rh < 2; rh++) {
                mx[mt][rh] = fmaxf(mx[mt][rh], __shfl_xor_sync(0xffffffffu, mx[mt][rh], 1));
                mx[mt][rh] = fmaxf(mx[mt][rh], __shfl_xor_sync(0xffffffffu, mx[mt][rh], 2));
            }
        if (tig == 0) {
            #pragma unroll
            for (int mt = 0; mt < 2; mt++)
                #pragma unroll
                for (int rh = 0; rh < 2; rh++)
                    red[(wr*32 + mt*16 + rh*8 + gid)*4 + wc] = mx[mt][rh];
        }
        __syncthreads();
        float mxf[2][2];
        #pragma unroll
        for (int mt = 0; mt < 2; mt++)
            #pragma unroll
            for (int rh = 0; rh < 2; rh++) {
                int r = wr*32 + mt*16 + rh*8 + gid;
                mxf[mt][rh] = fmaxf(fmaxf(red[r*4+0], red[r*4+1]), fmaxf(red[r*4+2], red[r*4+3]));
            }
        __syncthreads();
        float sume[2][2] = {{0,0},{0,0}};
        #pragma unroll
        for (int mt = 0; mt < 2; mt++)
            #pragma unroll
            for (int nt = 0; nt < 8; nt++)
                #pragma unroll
                for (int c = 0; c < 4; c++) {
                    int r = wr*32 + mt*16 + ((c>>1)*8) + gid;
                    float e = __expf(acc[mt][nt][c] - mxf[mt][c>>1]) * ms[r];
                    acc[mt][nt][c] = e;
                    sume[mt][c>>1] += e;
                }
        #pragma unroll
        for (int mt = 0; mt < 2; mt++)
            #pragma unroll
            for (int rh = 0; rh < 2; rh++) {
                sume[mt][rh] += __shfl_xor_sync(0xffffffffu, sume[mt][rh], 1);
                sume[mt][rh] += __shfl_xor_sync(0xffffffffu, sume[mt][rh], 2);
            }
        if (tig == 0) {
            #pragma unroll
            for (int mt = 0; mt < 2; mt++)
                #pragma unroll
                for (int rh = 0; rh < 2; rh++)
                    red[(wr*32 + mt*16 + rh*8 + gid)*4 + wc] = sume[mt][rh];
        }
        __syncthreads();
        float* bo = betas_out + (size_t)row0 * OO;
        #pragma unroll
        for (int mt = 0; mt < 2; mt++) {
            float inv[2];
            #pragma unroll
            for (int rh = 0; rh < 2; rh++) {
                int r = wr*32 + mt*16 + rh*8 + gid;
                float s = red[r*4+0] + red[r*4+1] + red[r*4+2] + red[r*4+3];
                inv[rh] = (s == 0.0f) ? 1.0f : __fdividef(1.0f, s);
            }
            int r0 = wr*32 + mt*16 + gid;
            #pragma unroll
            for (int nt = 0; nt < 8; nt++) {
                int cb = wc*64 + nt*8 + 2*tig;
                *(float2*)(bo + (size_t)r0 * OO + cb)     = make_float2(acc[mt][nt][0]*inv[0], acc[mt][nt][1]*inv[0]);
                *(float2*)(bo + (size_t)(r0+8) * OO + cb) = make_float2(acc[mt][nt][2]*inv[1], acc[mt][nt][3]*inv[1]);
            }
        }
    }
}

// ---------------------------------------------------------------------------
// alphas = masked softmax of g_vu over S, per batch
// ---------------------------------------------------------------------------
__global__ __launch_bounds__(1024)
void k_alphas(const float* __restrict__ mask, float* __restrict__ alphas)
{
    __shared__ float redA[32];
    __shared__ float redB[32];
    const int b = blockIdx.x;
    const int s = threadIdx.x;
    const int lane = s & 31, wid = s >> 5;

    float val = g_vu[b*SS + s];
    float m   = mask[b*SS + s];

    float wm = val;
    #pragma unroll
    for (int off = 16; off; off >>= 1) wm = fmaxf(wm, __shfl_xor_sync(0xffffffffu, wm, off));
    if (lane == 0) redA[wid] = wm;
    __syncthreads();
    if (wid == 0) {
        float t = redA[lane];
        #pragma unroll
        for (int off = 16; off; off >>= 1) t = fmaxf(t, __shfl_xor_sync(0xffffffffu, t, off));
        if (lane == 0) redA[0] = t;
    }
    __syncthreads();
    float mx = redA[0];

    float e = __expf(val - mx) * m;
    float wsm = e;
    #pragma unroll
    for (int off = 16; off; off >>= 1) wsm += __shfl_xor_sync(0xffffffffu, wsm, off);
    if (lane == 0) redB[wid] = wsm;
    __syncthreads();
    if (wid == 0) {
        float t = redB[lane];
        #pragma unroll
        for (int off = 16; off; off >>= 1) t += __shfl_xor_sync(0xffffffffu, t, off);
        if (lane == 0) redB[0] = t;
    }
    __syncthreads();
    float sum = redB[0];
    float inv = (sum == 0.0f) ? 1.0f : (1.0f / sum);
    alphas[b*SS + s] = e * inv;
}

// ---------------------------------------------------------------------------
// output partials over 64-row S-splits + deterministic reduce
// ---------------------------------------------------------------------------
__global__ __launch_bounds__(256)
void k_partial(const float* __restrict__ x, const float* __restrict__ alphas,
               const float* __restrict__ betas)
{
    __shared__ float as[64];
    __shared__ float4 red[4][64];
    const int b = blockIdx.x, sp = blockIdx.y;
    const int tid = threadIdx.x;
    const int o4 = tid & 63, sq = tid >> 6;
    const int s0 = sp * 64;

    if (tid < 64) as[tid] = alphas[b*SS + s0 + tid];
    __syncthreads();

    float4 acc = make_float4(0.f, 0.f, 0.f, 0.f);
    #pragma unroll 4
    for (int si = sq; si < 64; si += 4) {
        float a = as[si];
        if (a != 0.0f) {
            size_t base = ((size_t)b * SS + s0 + si) * OO + o4 * 4;
            float4 xv = *(const float4*)(x + base);
            float4 bv = *(const float4*)(betas + base);
            acc.x = fmaf(xv.x * a, bv.x, acc.x);
            acc.y = fmaf(xv.y * a, bv.y, acc.y);
            acc.z = fmaf(xv.z * a, bv.z, acc.z);
            acc.w = fmaf(xv.w * a, bv.w, acc.w);
        }
    }
    red[sq][o4] = acc;
    __syncthreads();
    if (tid < 64) {
        float4 r0 = red[0][tid], r1 = red[1][tid], r2 = red[2][tid], r3 = red[3][tid];
        float4 s = make_float4(r0.x + r1.x + r2.x + r3.x,
                               r0.y + r1.y + r2.y + r3.y,
                               r0.z + r1.z + r2.z + r3.z,
                               r0.w + r1.w + r2.w + r3.w);
        *(float4*)&g_part[((size_t)b * SPLITS + sp) * OO + tid * 4] = s;
    }
}

__global__ __launch_bounds__(256)
void k_reduce(float* __restrict__ out)
{
    const int idx = blockIdx.x * 256 + threadIdx.x;
    const int b = idx >> 8, o = idx & 255;
    float s = 0.0f;
    #pragma unroll
    for (int sp = 0; sp < SPLITS; sp++) s += g_part[((size_t)b * SPLITS + sp) * OO + o];
    out[idx] = s;
}

// ---------------------------------------------------------------------------
extern "C" void kernel_launch(void* const* d_in, const int* in_sizes, int n_in,
                              void* d_out, int out_size)
{
    const float* x    = (const float*)d_in[0];   // [B,S,D]
    const float* mask = (const float*)d_in[1];   // [B,S]
    const float* W    = (const float*)d_in[2];   // [D,A]
    const float* bv   = (const float*)d_in[3];   // [A]
    const float* u    = (const float*)d_in[4];   // [A]
    const float* Uo   = (const float*)d_in[5];   // [A,O]

    float* out    = (float*)d_out;               // [B,O]
    float* alphas = out + BB * OO;               // [B,S]
    float* betas  = alphas + BB * SS;            // [B,S,O]

    cudaFuncSetAttribute(k_fused, cudaFuncAttributeMaxDynamicSharedMemorySize, SMEM_BYTES);

    dim3 tg(8, 8, 2), tb(32, 8);
    k_prep<<<tg, tb>>>(W, Uo);
    k_fused<<<NROWS / TILE_R, 256, SMEM_BYTES>>>(x, mask, bv, u, betas);
    k_alphas<<<BB, 1024>>>(mask, alphas);
    dim3 g3(BB, SPLITS);
    k_partial<<<g3, 256>>>(x, alphas, betas);
    k_reduce<<<(BB * OO) / 256, 256>>>(out);
}

// round 11
// speedup vs baseline: 3.1174x; 1.1056x over previous
#include <cuda_runtime.h>
#include <cuda_fp16.h>
#include <math.h>
#include <stdint.h>

// Shapes (fixed)
#define BB 128
#define SS 1024
#define DD 256
#define AA 256
#define OO 256
#define NROWS (BB*SS)
#define SPLITS 16

#define TILE_R 64
#define LDA 264            // xs row stride in halfs (528B = 33*16) -> conflict-free
#define LDK 40             // weight row stride in halfs (80B = 5*16) -> conflict-free
#define CHUNK_B (256*LDK*2)   // 20480 bytes per 32-k weight chunk
#define NSTAGE 3

// smem byte offsets
#define O_XS   0               // 64*264*2 = 33792
#define O_WB   33792           // 3*20480 = 61440
#define O_BS   95232           // 256 f32
#define O_US   96256           // 256 f32
#define O_MS   97280           // 64 f32
#define O_RED  97536           // 64*4 f32
#define SMEM_BYTES 98560

// Scratch
__device__ float g_vu[NROWS];
__device__ float g_part[BB * SPLITS * OO];
__device__ __half g_Wh[DD * AA];    // W  transposed to [a][d], fp16
__device__ __half g_Uh[AA * OO];    // Uo transposed to [o][a], fp16

// ---------------------------------------------------------------------------
__device__ __forceinline__ uint32_t smem_u32(const void* p) {
    uint32_t a;
    asm("{ .reg .u64 t; cvta.to.shared.u64 t, %1; cvt.u32.u64 %0, t; }" : "=r"(a) : "l"(p));
    return a;
}
__device__ __forceinline__ void cp16(uint32_t dst, const void* src) {
    asm volatile("cp.async.cg.shared.global [%0], [%1], 16;" :: "r"(dst), "l"(src));
}
#define CP_COMMIT() asm volatile("cp.async.commit_group;" ::: "memory")
#define CP_WAIT0()  asm volatile("cp.async.wait_group 0;" ::: "memory")
#define CP_WAIT1()  asm volatile("cp.async.wait_group 1;" ::: "memory")

__device__ __forceinline__ void mma16(float* c, const uint32_t* a, uint32_t b0, uint32_t b1) {
    asm("mma.sync.aligned.m16n8k16.row.col.f32.f16.f16.f32 "
        "{%0,%1,%2,%3}, {%4,%5,%6,%7}, {%8,%9}, {%0,%1,%2,%3};"
        : "+f"(c[0]), "+f"(c[1]), "+f"(c[2]), "+f"(c[3])
        : "r"(a[0]), "r"(a[1]), "r"(a[2]), "r"(a[3]), "r"(b0), "r"(b1));
}
__device__ __forceinline__ void ldm4(uint32_t* d, uint32_t addr) {
    asm volatile("ldmatrix.sync.aligned.m8n8.x4.shared.b16 {%0,%1,%2,%3}, [%4];"
        : "=r"(d[0]), "=r"(d[1]), "=r"(d[2]), "=r"(d[3]) : "r"(addr));
}

// issue one 32k x 256n fp16 chunk: 256 threads, 4 cp16 each
__device__ __forceinline__ void issue_chunk(uint32_t dst, const __half* gsrc, int tid) {
    const __half* s = gsrc + tid * 256;
    uint32_t d = dst + (uint32_t)(tid * LDK * 2);
    #pragma unroll
    for (int p = 0; p < 4; p++) cp16(d + p * 16, s + p * 8);
    CP_COMMIT();
}

// one 32-k chunk of MMAs (two 16-k steps), ldmatrix fragment loads
__device__ __forceinline__ void compute_chunk(float acc[2][8][4],
        uint32_t xs_u32, uint32_t wb_cur, int kbase,
        uint32_t a_off0, uint32_t a_off1, uint32_t b_off)
{
    #pragma unroll
    for (int ks = 0; ks < 2; ks++) {
        const uint32_t kb2 = (uint32_t)(kbase + ks * 16) * 2u;
        uint32_t a0[4], a1[4];
        ldm4(a0, xs_u32 + a_off0 * 2u + kb2);
        ldm4(a1, xs_u32 + a_off1 * 2u + kb2);
        #pragma unroll
        for (int p = 0; p < 4; p++) {
            uint32_t b[4];
            ldm4(b, wb_cur + (b_off + (uint32_t)(p * 16 * LDK)) * 2u + (uint32_t)(ks * 32));
            mma16(acc[0][2*p],   a0, b[0], b[1]);
            mma16(acc[1][2*p],   a1, b[0], b[1]);
            mma16(acc[0][2*p+1], a0, b[2], b[3]);
            mma16(acc[1][2*p+1], a1, b[2], b[3]);
        }
    }
}

// 8 chunks, 3-stage ring, ONE sync per chunk. Chunks 0,1 pre-issued into bufs 0,1.
__device__ __forceinline__ void gemm_loop(float acc[2][8][4], const __half* __restrict__ gW,
        uint32_t xs_u32, uint32_t wb_u32,
        uint32_t a_off0, uint32_t a_off1, uint32_t b_off, int tid)
{
    for (int kc = 0; kc < 8; kc++) {
        if (kc < 7) CP_WAIT1(); else CP_WAIT0();
        __syncthreads();                       // chunk kc visible; buf (kc+2)%3 free
        if (kc + 2 < 8)
            issue_chunk(wb_u32 + (uint32_t)((kc + 2) % NSTAGE) * CHUNK_B,
                        gW + (kc + 2) * 32, tid);
        compute_chunk(acc, xs_u32, wb_u32 + (uint32_t)(kc % NSTAGE) * CHUNK_B,
                      kc * 32, a_off0, a_off1, b_off);
    }
}

// ---------------------------------------------------------------------------
// Transpose + fp16 convert: g_Wh[a][d] = W[d][a], g_Uh[o][a] = Uo[a][o]
// ---------------------------------------------------------------------------
__global__ void k_prep(const float* __restrict__ W, const float* __restrict__ Uo)
{
    __shared__ float t[32][33];
    const float* src = blockIdx.z ? Uo : W;
    __half* dst = blockIdx.z ? g_Uh : g_Wh;
    int x0 = blockIdx.x * 32, y0 = blockIdx.y * 32;
    #pragma unroll
    for (int i = 0; i < 32; i += 8)
        t[threadIdx.y + i][threadIdx.x] = src[(y0 + threadIdx.y + i) * 256 + x0 + threadIdx.x];
    __syncthreads();
    #pragma unroll
    for (int i = 0; i < 32; i += 8)
        dst[(x0 + threadIdx.y + i) * 256 + y0 + threadIdx.x] = __float2half_rn(t[threadIdx.x][threadIdx.y + i]);
}

// ---------------------------------------------------------------------------
// Fused kernel: 64-row tile, 256 threads, fp16 MMA + ldmatrix, occ 2
// ---------------------------------------------------------------------------
__global__ void __launch_bounds__(256, 2)
k_fused(const float* __restrict__ x, const float* __restrict__ mask,
        const float* __restrict__ bvec, const float* __restrict__ u,
        float* __restrict__ betas_out)
{
    extern __shared__ char smc[];
    __half* xs  = (__half*)(smc + O_XS);
    float* bs   = (float*)(smc + O_BS);
    float* us   = (float*)(smc + O_US);
    float* ms   = (float*)(smc + O_MS);
    float* red  = (float*)(smc + O_RED);     // [64][4]

    const uint32_t smb    = smem_u32(smc);
    const uint32_t xs_u32 = smb + O_XS;
    const uint32_t wb_u32 = smb + O_WB;

    const int tid  = threadIdx.x;
    const int lane = tid & 31;
    const int wid  = tid >> 5;
    const int wr   = wid >> 2;       // 0..1: 32-row stripe
    const int wc   = wid & 3;        // 0..3: 64-col quarter
    const int gid  = lane >> 2;
    const int tig  = lane & 3;
    const int row0 = blockIdx.x * TILE_R;

    // ldmatrix per-lane offsets (in halfs)
    const int l7 = lane & 7, l3 = (lane >> 3) & 1, l4 = (lane >> 4) & 1;
    const uint32_t a_off0 = (uint32_t)((wr*32 +  0 + l7 + l3*8) * LDA + l4*8);
    const uint32_t a_off1 = (uint32_t)((wr*32 + 16 + l7 + l3*8) * LDA + l4*8);
    const uint32_t b_off  = (uint32_t)((wc*64 + l7 + l4*8) * LDK + l3*8);

    // headers
    bs[tid] = bvec[tid];
    us[tid] = u[tid];
    if (tid < TILE_R) ms[tid] = mask[row0 + tid];

    // async-prefetch W chunks 0,1; then convert x tile to fp16 smem
    issue_chunk(wb_u32, g_Wh, tid);
    issue_chunk(wb_u32 + CHUNK_B, g_Wh + 32, tid);
    {
        const float* xg = x + (size_t)row0 * DD;
        #pragma unroll
        for (int i = 0; i < 16; i++) {
            int idx = tid + i * 256;             // 4096 float4s
            int row = idx >> 6, c4 = (idx & 63) * 4;
            float4 v = *(const float4*)(xg + row * 256 + c4);
            *(__half2*)(xs + row * LDA + c4)     = __floats2half2_rn(v.x, v.y);
            *(__half2*)(xs + row * LDA + c4 + 2) = __floats2half2_rn(v.z, v.w);
        }
    }

    float acc[2][8][4];

    // ---------------- GEMM1: t = x @ W ----------------
    #pragma unroll
    for (int mt = 0; mt < 2; mt++)
        #pragma unroll
        for (int nt = 0; nt < 8; nt++)
            #pragma unroll
            for (int c = 0; c < 4; c++) acc[mt][nt][c] = 0.0f;

    gemm_loop(acc, g_Wh, xs_u32, wb_u32, a_off0, a_off1, b_off, tid);
    __syncthreads();                 // last-chunk buffer free before Uo prefetch; xs reads done

    // prefetch Uo chunks 0,1 during epilogue1
    issue_chunk(wb_u32, g_Uh, tid);
    issue_chunk(wb_u32 + CHUNK_B, g_Uh + 32, tid);

    // ---------------- epilogue1 (registers): bias + normalize + tanh + vu; v->xs fp16
    {
        float ss[2][2] = {{0,0},{0,0}};
        #pragma unroll
        for (int mt = 0; mt < 2; mt++)
            #pragma unroll
            for (int nt = 0; nt < 8; nt++)
                #pragma unroll
                for (int c = 0; c < 4; c++) {
                    int col = wc*64 + nt*8 + 2*tig + (c & 1);
                    float t = acc[mt][nt][c] + bs[col];
                    acc[mt][nt][c] = t;
                    ss[mt][c>>1] = fmaf(t, t, ss[mt][c>>1]);
                }
        #pragma unroll
        for (int mt = 0; mt < 2; mt++)
            #pragma unroll
            for (int rh = 0; rh < 2; rh++) {
                ss[mt][rh] += __shfl_xor_sync(0xffffffffu, ss[mt][rh], 1);
                ss[mt][rh] += __shfl_xor_sync(0xffffffffu, ss[mt][rh], 2);
            }
        if (tig == 0) {
            #pragma unroll
            for (int mt = 0; mt < 2; mt++)
                #pragma unroll
                for (int rh = 0; rh < 2; rh++)
                    red[(wr*32 + mt*16 + rh*8 + gid)*4 + wc] = ss[mt][rh];
        }
        __syncthreads();
        float invn[2][2];
        #pragma unroll
        for (int mt = 0; mt < 2; mt++)
            #pragma unroll
            for (int rh = 0; rh < 2; rh++) {
                int r = wr*32 + mt*16 + rh*8 + gid;
                float s = red[r*4+0] + red[r*4+1] + red[r*4+2] + red[r*4+3];
                invn[mt][rh] = 1.0f / fmaxf(sqrtf(s), 1e-12f);
            }
        __syncthreads();                     // red free for reuse
        float vu[2][2] = {{0,0},{0,0}};
        #pragma unroll
        for (int mt = 0; mt < 2; mt++)
            #pragma unroll
            for (int nt = 0; nt < 8; nt++) {
                #pragma unroll
                for (int c = 0; c < 4; c++) {
                    int col = wc*64 + nt*8 + 2*tig + (c & 1);
                    float a = acc[mt][nt][c] * invn[mt][c>>1];   // |a| <= 1
                    float e = __expf(2.0f * a);
                    float v = __fdividef(e - 1.0f, e + 1.0f);
                    acc[mt][nt][c] = v;
                    vu[mt][c>>1] = fmaf(v, us[col], vu[mt][c>>1]);
                }
                int cb = wc*64 + nt*8 + 2*tig;
                int r0 = wr*32 + mt*16 + gid;
                *(__half2*)(xs + r0*LDA + cb)     = __floats2half2_rn(acc[mt][nt][0], acc[mt][nt][1]);
                *(__half2*)(xs + (r0+8)*LDA + cb) = __floats2half2_rn(acc[mt][nt][2], acc[mt][nt][3]);
            }
        #pragma unroll
        for (int mt = 0; mt < 2; mt++)
            #pragma unroll
            for (int rh = 0; rh < 2; rh++) {
                vu[mt][rh] += __shfl_xor_sync(0xffffffffu, vu[mt][rh], 1);
                vu[mt][rh] += __shfl_xor_sync(0xffffffffu, vu[mt][rh], 2);
            }
        if (tig == 0) {
            #pragma unroll
            for (int mt = 0; mt < 2; mt++)
                #pragma unroll
                for (int rh = 0; rh < 2; rh++)
                    red[(wr*32 + mt*16 + rh*8 + gid)*4 + wc] = vu[mt][rh];
        }
        __syncthreads();
        if (wc == 0 && tig == 0) {
            #pragma unroll
            for (int mt = 0; mt < 2; mt++)
                #pragma unroll
                for (int rh = 0; rh < 2; rh++) {
                    int r = wr*32 + mt*16 + rh*8 + gid;
                    float s = red[r*4+0] + red[r*4+1] + red[r*4+2] + red[r*4+3];
                    g_vu[row0 + r] = s * ms[r];
                }
        }
    }

    // ---------------- GEMM2: vuo = v @ Uo ----------------
    #pragma unroll
    for (int mt = 0; mt < 2; mt++)
        #pragma unroll
        for (int nt = 0; nt < 8; nt++)
            #pragma unroll
            for (int c = 0; c < 4; c++) acc[mt][nt][c] = 0.0f;

    gemm_loop(acc, g_Uh, xs_u32, wb_u32, a_off0, a_off1, b_off, tid);

    // ---------------- epilogue2 (registers): mask + softmax over O -> betas
    {
        float mx[2][2] = {{-3.4e38f,-3.4e38f},{-3.4e38f,-3.4e38f}};
        #pragma unroll
        for (int mt = 0; mt < 2; mt++)
            #pragma unroll
            for (int nt = 0; nt < 8; nt++)
                #pragma unroll
                for (int c = 0; c < 4; c++) {
                    int r = wr*32 + mt*16 + ((c>>1)*8) + gid;
                    float v = acc[mt][nt][c] * ms[r];
                    acc[mt][nt][c] = v;
                    mx[mt][c>>1] = fmaxf(mx[mt][c>>1], v);
                }
        #pragma unroll
        for (int mt = 0; mt < 2; mt++)
            #pragma unroll
            for (int rh = 0; rh < 2; rh++) {
                mx[mt][rh] = fmaxf(mx[mt][rh], __shfl_xor_sync(0xffffffffu, mx[mt][rh], 1));
                mx[mt][rh] = fmaxf(mx[mt][rh], __shfl_xor_sync(0xffffffffu, mx[mt][rh], 2));
            }
        __syncthreads();                     // all reads of red (ep1) done everywhere
        if (tig == 0) {
            #pragma unroll
            for (int mt = 0; mt < 2; mt++)
                #pragma unroll
                for (int rh = 0; rh < 2; rh++)
                    red[(wr*32 + mt*16 + rh*8 + gid)*4 + wc] = mx[mt][rh];
        }
        __syncthreads();
        float mxf[2][2];
        #pragma unroll
        for (int mt = 0; mt < 2; mt++)
            #pragma unroll
            for (int rh = 0; rh < 2; rh++) {
                int r = wr*32 + mt*16 + rh*8 + gid;
                mxf[mt][rh] = fmaxf(fmaxf(red[r*4+0], red[r*4+1]), fmaxf(red[r*4+2], red[r*4+3]));
            }
        __syncthreads();
        float sume[2][2] = {{0,0},{0,0}};
        #pragma unroll
        for (int mt = 0; mt < 2; mt++)
            #pragma unroll
            for (int nt = 0; nt < 8; nt++)
                #pragma unroll
                for (int c = 0; c < 4; c++) {
                    int r = wr*32 + mt*16 + ((c>>1)*8) + gid;
                    float e = __expf(acc[mt][nt][c] - mxf[mt][c>>1]) * ms[r];
                    acc[mt][nt][c] = e;
                    sume[mt][c>>1] += e;
                }
        #pragma unroll
        for (int mt = 0; mt < 2; mt++)
            #pragma unroll
            for (int rh = 0; rh < 2; rh++) {
                sume[mt][rh] += __shfl_xor_sync(0xffffffffu, sume[mt][rh], 1);
                sume[mt][rh] += __shfl_xor_sync(0xffffffffu, sume[mt][rh], 2);
            }
        if (tig == 0) {
            #pragma unroll
            for (int mt = 0; mt < 2; mt++)
                #pragma unroll
                for (int rh = 0; rh < 2; rh++)
                    red[(wr*32 + mt*16 + rh*8 + gid)*4 + wc] = sume[mt][rh];
        }
        __syncthreads();
        float* bo = betas_out + (size_t)row0 * OO;
        #pragma unroll
        for (int mt = 0; mt < 2; mt++) {
            float inv[2];
            #pragma unroll
            for (int rh = 0; rh < 2; rh++) {
                int r = wr*32 + mt*16 + rh*8 + gid;
                float s = red[r*4+0] + red[r*4+1] + red[r*4+2] + red[r*4+3];
                inv[rh] = (s == 0.0f) ? 1.0f : __fdividef(1.0f, s);
            }
            int r0 = wr*32 + mt*16 + gid;
            #pragma unroll
            for (int nt = 0; nt < 8; nt++) {
                int cb = wc*64 + nt*8 + 2*tig;
                *(float2*)(bo + (size_t)r0 * OO + cb)     = make_float2(acc[mt][nt][0]*inv[0], acc[mt][nt][1]*inv[0]);
                *(float2*)(bo + (size_t)(r0+8) * OO + cb) = make_float2(acc[mt][nt][2]*inv[1], acc[mt][nt][3]*inv[1]);
            }
        }
    }
}

// ---------------------------------------------------------------------------
// alphas = masked softmax of g_vu over S, per batch
// ---------------------------------------------------------------------------
__global__ __launch_bounds__(1024)
void k_alphas(const float* __restrict__ mask, float* __restrict__ alphas)
{
    __shared__ float redA[32];
    __shared__ float redB[32];
    const int b = blockIdx.x;
    const int s = threadIdx.x;
    const int lane = s & 31, wid = s >> 5;

    float val = g_vu[b*SS + s];
    float m   = mask[b*SS + s];

    float wm = val;
    #pragma unroll
    for (int off = 16; off; off >>= 1) wm = fmaxf(wm, __shfl_xor_sync(0xffffffffu, wm, off));
    if (lane == 0) redA[wid] = wm;
    __syncthreads();
    if (wid == 0) {
        float t = redA[lane];
        #pragma unroll
        for (int off = 16; off; off >>= 1) t = fmaxf(t, __shfl_xor_sync(0xffffffffu, t, off));
        if (lane == 0) redA[0] = t;
    }
    __syncthreads();
    float mx = redA[0];

    float e = __expf(val - mx) * m;
    float wsm = e;
    #pragma unroll
    for (int off = 16; off; off >>= 1) wsm += __shfl_xor_sync(0xffffffffu, wsm, off);
    if (lane == 0) redB[wid] = wsm;
    __syncthreads();
    if (wid == 0) {
        float t = redB[lane];
        #pragma unroll
        for (int off = 16; off; off >>= 1) t += __shfl_xor_sync(0xffffffffu, t, off);
        if (lane == 0) redB[0] = t;
    }
    __syncthreads();
    float sum = redB[0];
    float inv = (sum == 0.0f) ? 1.0f : (1.0f / sum);
    alphas[b*SS + s] = e * inv;
}

// ---------------------------------------------------------------------------
// output partials over 64-row S-splits + deterministic reduce
// ---------------------------------------------------------------------------
__global__ __launch_bounds__(256)
void k_partial(const float* __restrict__ x, const float* __restrict__ alphas,
               const float* __restrict__ betas)
{
    __shared__ float as[64];
    __shared__ float4 red[4][64];
    const int b = blockIdx.x, sp = blockIdx.y;
    const int tid = threadIdx.x;
    const int o4 = tid & 63, sq = tid >> 6;
    const int s0 = sp * 64;

    if (tid < 64) as[tid] = alphas[b*SS + s0 + tid];
    __syncthreads();

    float4 acc = make_float4(0.f, 0.f, 0.f, 0.f);
    #pragma unroll 4
    for (int si = sq; si < 64; si += 4) {
        float a = as[si];
        if (a != 0.0f) {
            size_t base = ((size_t)b * SS + s0 + si) * OO + o4 * 4;
            float4 xv = *(const float4*)(x + base);
            float4 bv = *(const float4*)(betas + base);
            acc.x = fmaf(xv.x * a, bv.x, acc.x);
            acc.y = fmaf(xv.y * a, bv.y, acc.y);
            acc.z = fmaf(xv.z * a, bv.z, acc.z);
            acc.w = fmaf(xv.w * a, bv.w, acc.w);
        }
    }
    red[sq][o4] = acc;
    __syncthreads();
    if (tid < 64) {
        float4 r0 = red[0][tid], r1 = red[1][tid], r2 = red[2][tid], r3 = red[3][tid];
        float4 s = make_float4(r0.x + r1.x + r2.x + r3.x,
                               r0.y + r1.y + r2.y + r3.y,
                               r0.z + r1.z + r2.z + r3.z,
                               r0.w + r1.w + r2.w + r3.w);
        *(float4*)&g_part[((size_t)b * SPLITS + sp) * OO + tid * 4] = s;
    }
}

__global__ __launch_bounds__(256)
void k_reduce(float* __restrict__ out)
{
    const int idx = blockIdx.x * 256 + threadIdx.x;
    const int b = idx >> 8, o = idx & 255;
    float s = 0.0f;
    #pragma unroll
    for (int sp = 0; sp < SPLITS; sp++) s += g_part[((size_t)b * SPLITS + sp) * OO + o];
    out[idx] = s;
}

// ---------------------------------------------------------------------------
extern "C" void kernel_launch(void* const* d_in, const int* in_sizes, int n_in,
                              void* d_out, int out_size)
{
    const float* x    = (const float*)d_in[0];   // [B,S,D]
    const float* mask = (const float*)d_in[1];   // [B,S]
    const float* W    = (const float*)d_in[2];   // [D,A]
    const float* bv   = (const float*)d_in[3];   // [A]
    const float* u    = (const float*)d_in[4];   // [A]
    const float* Uo   = (const float*)d_in[5];   // [A,O]

    float* out    = (float*)d_out;               // [B,O]
    float* alphas = out + BB * OO;               // [B,S]
    float* betas  = alphas + BB * SS;            // [B,S,O]

    cudaFuncSetAttribute(k_fused, cudaFuncAttributeMaxDynamicSharedMemorySize, SMEM_BYTES);

    dim3 tg(8, 8, 2), tb(32, 8);
    k_prep<<<tg, tb>>>(W, Uo);
    k_fused<<<NROWS / TILE_R, 256, SMEM_BYTES>>>(x, mask, bv, u, betas);
    k_alphas<<<BB, 1024>>>(mask, alphas);
    dim3 g3(BB, SPLITS);
    k_partial<<<g3, 256>>>(x, alphas, betas);
    k_reduce<<<(BB * OO) / 256, 256>>>(out);
}

// round 13
// speedup vs baseline: 3.3952x; 1.0891x over previous
#include <cuda_runtime.h>
#include <cuda_fp16.h>
#include <math.h>
#include <stdint.h>

// Shapes (fixed)
#define BB 128
#define SS 1024
#define DD 256
#define AA 256
#define OO 256
#define NROWS (BB*SS)

#define TILE_R 64
#define LDA 264            // xs row stride in halfs (528B) -> conflict-free
#define LDK 40             // weight row stride in halfs (80B) -> conflict-free
#define CHUNK_B (256*LDK*2)   // 20480 bytes per 32-k weight chunk
#define NSTAGE 3

// smem byte offsets
#define O_XS   0               // 64*264*2 = 33792
#define O_WB   33792           // 3*20480 = 61440
#define O_BS   95232           // 256 f32
#define O_US   96256           // 256 f32
#define O_MS   97280           // 64 f32
#define O_RED  97536           // 64*4 f32
#define O_VUS  98560           // 64 f32 (tile vu values)
#define O_MTW  98816           // 2 f32 warp maxes (+pad)
#define O_QS   98832           // 64 f32 (q_s)
#define O_P4   99088           // 4*64 float4 = 4096
#define SMEM_BYTES 103184

// Scratch
__device__ float g_vu[NROWS];
__device__ float g_part[NROWS/TILE_R * OO];   // per-tile output partials
__device__ float g_mt[NROWS/TILE_R];          // per-tile local max
__device__ float g_M[BB];                     // per-batch global max
__device__ float g_invZ[BB];                  // per-batch 1/Z (or 1 if Z==0)
__device__ __half g_Wh[DD * AA];    // W  transposed to [a][d], fp16
__device__ __half g_Uh[AA * OO];    // Uo transposed to [o][a], fp16

// ---------------------------------------------------------------------------
__device__ __forceinline__ uint32_t smem_u32(const void* p) {
    uint32_t a;
    asm("{ .reg .u64 t; cvta.to.shared.u64 t, %1; cvt.u32.u64 %0, t; }" : "=r"(a) : "l"(p));
    return a;
}
__device__ __forceinline__ void cp16(uint32_t dst, const void* src) {
    asm volatile("cp.async.cg.shared.global [%0], [%1], 16;" :: "r"(dst), "l"(src));
}
#define CP_COMMIT() asm volatile("cp.async.commit_group;" ::: "memory")
#define CP_WAIT0()  asm volatile("cp.async.wait_group 0;" ::: "memory")
#define CP_WAIT1()  asm volatile("cp.async.wait_group 1;" ::: "memory")

__device__ __forceinline__ void mma16(float* c, const uint32_t* a, uint32_t b0, uint32_t b1) {
    asm("mma.sync.aligned.m16n8k16.row.col.f32.f16.f16.f32 "
        "{%0,%1,%2,%3}, {%4,%5,%6,%7}, {%8,%9}, {%0,%1,%2,%3};"
        : "+f"(c[0]), "+f"(c[1]), "+f"(c[2]), "+f"(c[3])
        : "r"(a[0]), "r"(a[1]), "r"(a[2]), "r"(a[3]), "r"(b0), "r"(b1));
}
__device__ __forceinline__ void ldm4(uint32_t* d, uint32_t addr) {
    asm volatile("ldmatrix.sync.aligned.m8n8.x4.shared.b16 {%0,%1,%2,%3}, [%4];"
        : "=r"(d[0]), "=r"(d[1]), "=r"(d[2]), "=r"(d[3]) : "r"(addr));
}
__device__ __forceinline__ float tanh_fast(float a) {
    float v;
    asm("tanh.approx.f32 %0, %1;" : "=f"(v) : "f"(a));
    return v;
}

// issue one 32k x 256n fp16 chunk: 256 threads, 4 cp16 each
__device__ __forceinline__ void issue_chunk(uint32_t dst, const __half* gsrc, int tid) {
    const __half* s = gsrc + tid * 256;
    uint32_t d = dst + (uint32_t)(tid * LDK * 2);
    #pragma unroll
    for (int p = 0; p < 4; p++) cp16(d + p * 16, s + p * 8);
    CP_COMMIT();
}

// one 32-k chunk of MMAs (two 16-k steps), ldmatrix fragment loads
__device__ __forceinline__ void compute_chunk(float acc[2][8][4],
        uint32_t xs_u32, uint32_t wb_cur, int kbase,
        uint32_t a_off0, uint32_t a_off1, uint32_t b_off)
{
    #pragma unroll
    for (int ks = 0; ks < 2; ks++) {
        const uint32_t kb2 = (uint32_t)(kbase + ks * 16) * 2u;
        uint32_t a0[4], a1[4];
        ldm4(a0, xs_u32 + a_off0 * 2u + kb2);
        ldm4(a1, xs_u32 + a_off1 * 2u + kb2);
        #pragma unroll
        for (int p = 0; p < 4; p++) {
            uint32_t b[4];
            ldm4(b, wb_cur + (b_off + (uint32_t)(p * 16 * LDK)) * 2u + (uint32_t)(ks * 32));
            mma16(acc[0][2*p],   a0, b[0], b[1]);
            mma16(acc[1][2*p],   a1, b[0], b[1]);
            mma16(acc[0][2*p+1], a0, b[2], b[3]);
            mma16(acc[1][2*p+1], a1, b[2], b[3]);
        }
    }
}

// 8 chunks, 3-stage ring, ONE sync per chunk. Chunks 0,1 pre-issued into bufs 0,1.
__device__ __forceinline__ void gemm_loop(float acc[2][8][4], const __half* __restrict__ gW,
        uint32_t xs_u32, uint32_t wb_u32,
        uint32_t a_off0, uint32_t a_off1, uint32_t b_off, int tid)
{
    for (int kc = 0; kc < 8; kc++) {
        if (kc < 7) CP_WAIT1(); else CP_WAIT0();
        __syncthreads();                       // chunk kc visible; buf (kc+2)%3 free
        if (kc + 2 < 8)
            issue_chunk(wb_u32 + (uint32_t)((kc + 2) % NSTAGE) * CHUNK_B,
                        gW + (kc + 2) * 32, tid);
        compute_chunk(acc, xs_u32, wb_u32 + (uint32_t)(kc % NSTAGE) * CHUNK_B,
                      kc * 32, a_off0, a_off1, b_off);
    }
}

// ---------------------------------------------------------------------------
// Transpose + fp16 convert: g_Wh[a][d] = W[d][a], g_Uh[o][a] = Uo[a][o]
// ---------------------------------------------------------------------------
__global__ void k_prep(const float* __restrict__ W, const float* __restrict__ Uo)
{
    __shared__ float t[32][33];
    const float* src = blockIdx.z ? Uo : W;
    __half* dst = blockIdx.z ? g_Uh : g_Wh;
    int x0 = blockIdx.x * 32, y0 = blockIdx.y * 32;
    #pragma unroll
    for (int i = 0; i < 32; i += 8)
        t[threadIdx.y + i][threadIdx.x] = src[(y0 + threadIdx.y + i) * 256 + x0 + threadIdx.x];
    __syncthreads();
    #pragma unroll
    for (int i = 0; i < 32; i += 8)
        dst[(x0 + threadIdx.y + i) * 256 + y0 + threadIdx.x] = __float2half_rn(t[threadIdx.x][threadIdx.y + i]);
}

// ---------------------------------------------------------------------------
// Fused kernel: 64-row tile, 256 threads, fp16 MMA + ldmatrix, occ 2.
// Produces betas, g_vu, and flash-style output partials g_part/g_mt.
// ---------------------------------------------------------------------------
__global__ void __launch_bounds__(256, 2)
k_fused(const float* __restrict__ x, const float* __restrict__ mask,
        const float* __restrict__ bvec, const float* __restrict__ u,
        float* __restrict__ betas_out)
{
    extern __shared__ char smc[];
    __half* xs  = (__half*)(smc + O_XS);
    float* bs   = (float*)(smc + O_BS);
    float* us   = (float*)(smc + O_US);
    float* ms   = (float*)(smc + O_MS);
    float* red  = (float*)(smc + O_RED);     // [64][4]
    float* vus  = (float*)(smc + O_VUS);     // [64] masked vu
    float* mtw  = (float*)(smc + O_MTW);     // [2] warp maxes
    float* qs   = (float*)(smc + O_QS);      // [64] q_s
    float4* p4  = (float4*)(smc + O_P4);     // [4][64]

    const uint32_t smb    = smem_u32(smc);
    const uint32_t xs_u32 = smb + O_XS;
    const uint32_t wb_u32 = smb + O_WB;

    const int tid  = threadIdx.x;
    const int lane = tid & 31;
    const int wid  = tid >> 5;
    const int wr   = wid >> 2;       // 0..1: 32-row stripe
    const int wc   = wid & 3;        // 0..3: 64-col quarter
    const int gid  = lane >> 2;
    const int tig  = lane & 3;
    const int row0 = blockIdx.x * TILE_R;

    // ldmatrix per-lane offsets (in halfs)
    const int l7 = lane & 7, l3 = (lane >> 3) & 1, l4 = (lane >> 4) & 1;
    const uint32_t a_off0 = (uint32_t)((wr*32 +  0 + l7 + l3*8) * LDA + l4*8);
    const uint32_t a_off1 = (uint32_t)((wr*32 + 16 + l7 + l3*8) * LDA + l4*8);
    const uint32_t b_off  = (uint32_t)((wc*64 + l7 + l4*8) * LDK + l3*8);

    // headers
    bs[tid] = bvec[tid];
    us[tid] = u[tid];
    if (tid < TILE_R) ms[tid] = mask[row0 + tid];

    // async-prefetch W chunks 0,1; then convert x tile to fp16 smem
    issue_chunk(wb_u32, g_Wh, tid);
    issue_chunk(wb_u32 + CHUNK_B, g_Wh + 32, tid);
    {
        const float* xg = x + (size_t)row0 * DD;
        #pragma unroll
        for (int i = 0; i < 16; i++) {
            int idx = tid + i * 256;             // 4096 float4s
            int row = idx >> 6, c4 = (idx & 63) * 4;
            float4 v = *(const float4*)(xg + row * 256 + c4);
            *(__half2*)(xs + row * LDA + c4)     = __floats2half2_rn(v.x, v.y);
            *(__half2*)(xs + row * LDA + c4 + 2) = __floats2half2_rn(v.z, v.w);
        }
    }

    float acc[2][8][4];

    // ---------------- GEMM1: t = x @ W ----------------
    #pragma unroll
    for (int mt = 0; mt < 2; mt++)
        #pragma unroll
        for (int nt = 0; nt < 8; nt++)
            #pragma unroll
            for (int c = 0; c < 4; c++) acc[mt][nt][c] = 0.0f;

    gemm_loop(acc, g_Wh, xs_u32, wb_u32, a_off0, a_off1, b_off, tid);
    __syncthreads();                 // last-chunk buffer free before Uo prefetch; xs reads done

    // prefetch Uo chunks 0,1 during epilogue1
    issue_chunk(wb_u32, g_Uh, tid);
    issue_chunk(wb_u32 + CHUNK_B, g_Uh + 32, tid);

    // ---------------- epilogue1 (registers): bias + normalize + tanh + vu; v->xs fp16
    {
        float ss[2][2] = {{0,0},{0,0}};
        #pragma unroll
        for (int mt = 0; mt < 2; mt++)
            #pragma unroll
            for (int nt = 0; nt < 8; nt++)
                #pragma unroll
                for (int c = 0; c < 4; c++) {
                    int col = wc*64 + nt*8 + 2*tig + (c & 1);
                    float t = acc[mt][nt][c] + bs[col];
                    acc[mt][nt][c] = t;
                    ss[mt][c>>1] = fmaf(t, t, ss[mt][c>>1]);
                }
        #pragma unroll
        for (int mt = 0; mt < 2; mt++)
            #pragma unroll
            for (int rh = 0; rh < 2; rh++) {
                ss[mt][rh] += __shfl_xor_sync(0xffffffffu, ss[mt][rh], 1);
                ss[mt][rh] += __shfl_xor_sync(0xffffffffu, ss[mt][rh], 2);
            }
        if (tig == 0) {
            #pragma unroll
            for (int mt = 0; mt < 2; mt++)
                #pragma unroll
                for (int rh = 0; rh < 2; rh++)
                    red[(wr*32 + mt*16 + rh*8 + gid)*4 + wc] = ss[mt][rh];
        }
        __syncthreads();
        float invn[2][2];
        #pragma unroll
        for (int mt = 0; mt < 2; mt++)
            #pragma unroll
            for (int rh = 0; rh < 2; rh++) {
                int r = wr*32 + mt*16 + rh*8 + gid;
                float s = red[r*4+0] + red[r*4+1] + red[r*4+2] + red[r*4+3];
                invn[mt][rh] = 1.0f / fmaxf(sqrtf(s), 1e-12f);
            }
        __syncthreads();                     // red free for reuse
        float vu[2][2] = {{0,0},{0,0}};
        #pragma unroll
        for (int mt = 0; mt < 2; mt++)
            #pragma unroll
            for (int nt = 0; nt < 8; nt++) {
                #pragma unroll
                for (int c = 0; c < 4; c++) {
                    int col = wc*64 + nt*8 + 2*tig + (c & 1);
                    float a = acc[mt][nt][c] * invn[mt][c>>1];   // |a| <= 1
                    float v = tanh_fast(a);
                    acc[mt][nt][c] = v;
                    vu[mt][c>>1] = fmaf(v, us[col], vu[mt][c>>1]);
                }
                int cb = wc*64 + nt*8 + 2*tig;
                int r0 = wr*32 + mt*16 + gid;
                *(__half2*)(xs + r0*LDA + cb)     = __floats2half2_rn(acc[mt][nt][0], acc[mt][nt][1]);
                *(__half2*)(xs + (r0+8)*LDA + cb) = __floats2half2_rn(acc[mt][nt][2], acc[mt][nt][3]);
            }
        #pragma unroll
        for (int mt = 0; mt < 2; mt++)
            #pragma unroll
            for (int rh = 0; rh < 2; rh++) {
                vu[mt][rh] += __shfl_xor_sync(0xffffffffu, vu[mt][rh], 1);
                vu[mt][rh] += __shfl_xor_sync(0xffffffffu, vu[mt][rh], 2);
            }
        if (tig == 0) {
            #pragma unroll
            for (int mt = 0; mt < 2; mt++)
                #pragma unroll
                for (int rh = 0; rh < 2; rh++)
                    red[(wr*32 + mt*16 + rh*8 + gid)*4 + wc] = vu[mt][rh];
        }
        __syncthreads();
        if (wc == 0 && tig == 0) {
            #pragma unroll
            for (int mt = 0; mt < 2; mt++)
                #pragma unroll
                for (int rh = 0; rh < 2; rh++) {
                    int r = wr*32 + mt*16 + rh*8 + gid;
                    float s = red[r*4+0] + red[r*4+1] + red[r*4+2] + red[r*4+3];
                    float sm = s * ms[r];
                    g_vu[row0 + r] = sm;
                    vus[r] = sm;
                }
        }
    }

    // ---------------- GEMM2: vuo = v @ Uo ----------------
    #pragma unroll
    for (int mt = 0; mt < 2; mt++)
        #pragma unroll
        for (int nt = 0; nt < 8; nt++)
            #pragma unroll
            for (int c = 0; c < 4; c++) acc[mt][nt][c] = 0.0f;

    gemm_loop(acc, g_Uh, xs_u32, wb_u32, a_off0, a_off1, b_off, tid);

    // ---------------- epilogue2 (registers): mask + softmax over O -> betas,
    //                  then flash-style output partial
    {
        // tile-local vu max (warps 0,1 reduce vus[64])
        if (wid < 2) {
            float vm = vus[lane + wid*32];
            #pragma unroll
            for (int off = 16; off; off >>= 1) vm = fmaxf(vm, __shfl_xor_sync(0xffffffffu, vm, off));
            if (lane == 0) mtw[wid] = vm;
        }

        float mx[2][2] = {{-3.4e38f,-3.4e38f},{-3.4e38f,-3.4e38f}};
        #pragma unroll
        for (int mt = 0; mt < 2; mt++)
            #pragma unroll
            for (int nt = 0; nt < 8; nt++)
                #pragma unroll
                for (int c = 0; c < 4; c++) {
                    int r = wr*32 + mt*16 + ((c>>1)*8) + gid;
                    float v = acc[mt][nt][c] * ms[r];
                    acc[mt][nt][c] = v;
                    mx[mt][c>>1] = fmaxf(mx[mt][c>>1], v);
                }
        #pragma unroll
        for (int mt = 0; mt < 2; mt++)
            #pragma unroll
            for (int rh = 0; rh < 2; rh++) {
                mx[mt][rh] = fmaxf(mx[mt][rh], __shfl_xor_sync(0xffffffffu, mx[mt][rh], 1));
                mx[mt][rh] = fmaxf(mx[mt][rh], __shfl_xor_sync(0xffffffffu, mx[mt][rh], 2));
            }
        __syncthreads();                     // red (ep1) reads done; mtw visible
        const float m_t = fmaxf(mtw[0], mtw[1]);
        // q_s = exp(vu_s - m_t) * mask_s   (betas carry their own 1/sum)
        if (tid < TILE_R) qs[tid] = __expf(vus[tid] - m_t) * ms[tid];
        if (tig == 0) {
            #pragma unroll
            for (int mt = 0; mt < 2; mt++)
                #pragma unroll
                for (int rh = 0; rh < 2; rh++)
                    red[(wr*32 + mt*16 + rh*8 + gid)*4 + wc] = mx[mt][rh];
        }
        __syncthreads();
        float mxf[2][2];
        #pragma unroll
        for (int mt = 0; mt < 2; mt++)
            #pragma unroll
            for (int rh = 0; rh < 2; rh++) {
                int r = wr*32 + mt*16 + rh*8 + gid;
                mxf[mt][rh] = fmaxf(fmaxf(red[r*4+0], red[r*4+1]), fmaxf(red[r*4+2], red[r*4+3]));
            }
        __syncthreads();
        float sume[2][2] = {{0,0},{0,0}};
        #pragma unroll
        for (int mt = 0; mt < 2; mt++)
            #pragma unroll
            for (int nt = 0; nt < 8; nt++)
                #pragma unroll
                for (int c = 0; c < 4; c++) {
                    int r = wr*32 + mt*16 + ((c>>1)*8) + gid;
                    float e = __expf(acc[mt][nt][c] - mxf[mt][c>>1]) * ms[r];
                    acc[mt][nt][c] = e;
                    sume[mt][c>>1] += e;
                }
        #pragma unroll
        for (int mt = 0; mt < 2; mt++)
            #pragma unroll
            for (int rh = 0; rh < 2; rh++) {
                sume[mt][rh] += __shfl_xor_sync(0xffffffffu, sume[mt][rh], 1);
                sume[mt][rh] += __shfl_xor_sync(0xffffffffu, sume[mt][rh], 2);
            }
        if (tig == 0) {
            #pragma unroll
            for (int mt = 0; mt < 2; mt++)
                #pragma unroll
                for (int rh = 0; rh < 2; rh++)
                    red[(wr*32 + mt*16 + rh*8 + gid)*4 + wc] = sume[mt][rh];
        }
        __syncthreads();
        float* bo = betas_out + (size_t)row0 * OO;
        #pragma unroll
        for (int mt = 0; mt < 2; mt++) {
            float inv[2];
            #pragma unroll
            for (int rh = 0; rh < 2; rh++) {
                int r = wr*32 + mt*16 + rh*8 + gid;
                float s = red[r*4+0] + red[r*4+1] + red[r*4+2] + red[r*4+3];
                inv[rh] = (s == 0.0f) ? 1.0f : __fdividef(1.0f, s);
            }
            int r0 = wr*32 + mt*16 + gid;
            #pragma unroll
            for (int nt = 0; nt < 8; nt++) {
                int cb = wc*64 + nt*8 + 2*tig;
                *(float2*)(bo + (size_t)r0 * OO + cb)     = make_float2(acc[mt][nt][0]*inv[0], acc[mt][nt][1]*inv[0]);
                *(float2*)(bo + (size_t)(r0+8) * OO + cb) = make_float2(acc[mt][nt][2]*inv[1], acc[mt][nt][3]*inv[1]);
            }
        }
        __syncthreads();                     // betas (global, block-visible) + qs ready

        // ---- in-kernel output partial: P_t[o] = sum_r qs[r]*betas[r][o]*x[r][o]
        {
            const int o4 = (tid & 63) * 4;
            const int rq = tid >> 6;
            float4 pa = make_float4(0.f, 0.f, 0.f, 0.f);
            #pragma unroll 4
            for (int r = rq; r < TILE_R; r += 4) {
                float q = qs[r];
                if (q != 0.0f) {
                    size_t base = ((size_t)(row0 + r)) * OO + o4;
                    float4 xv = *(const float4*)(x + base);
                    float4 bv = *(const float4*)(betas_out + base);
                    pa.x = fmaf(q * xv.x, bv.x, pa.x);
                    pa.y = fmaf(q * xv.y, bv.y, pa.y);
                    pa.z = fmaf(q * xv.z, bv.z, pa.z);
                    pa.w = fmaf(q * xv.w, bv.w, pa.w);
                }
            }
            p4[rq * 64 + (tid & 63)] = pa;
            __syncthreads();
            if (tid < 64) {
                float4 a0 = p4[tid], a1 = p4[64+tid], a2 = p4[128+tid], a3 = p4[192+tid];
                float4 s = make_float4(a0.x+a1.x+a2.x+a3.x, a0.y+a1.y+a2.y+a3.y,
                                       a0.z+a1.z+a2.z+a3.z, a0.w+a1.w+a2.w+a3.w);
                *(float4*)&g_part[(size_t)blockIdx.x * OO + tid * 4] = s;
            }
            if (tid == 0) g_mt[blockIdx.x] = m_t;
        }
    }
}

// ---------------------------------------------------------------------------
// alphas = masked softmax of g_vu over S, per batch; exports M_b, 1/Z_b
// ---------------------------------------------------------------------------
__global__ __launch_bounds__(1024)
void k_alphas(const float* __restrict__ mask, float* __restrict__ alphas)
{
    __shared__ float redA[32];
    __shared__ float redB[32];
    const int b = blockIdx.x;
    const int s = threadIdx.x;
    const int lane = s & 31, wid = s >> 5;

    float val = g_vu[b*SS + s];
    float m   = mask[b*SS + s];

    float wm = val;
    #pragma unroll
    for (int off = 16; off; off >>= 1) wm = fmaxf(wm, __shfl_xor_sync(0xffffffffu, wm, off));
    if (lane == 0) redA[wid] = wm;
    __syncthreads();
    if (wid == 0) {
        float t = redA[lane];
        #pragma unroll
        for (int off = 16; off; off >>= 1) t = fmaxf(t, __shfl_xor_sync(0xffffffffu, t, off));
        if (lane == 0) redA[0] = t;
    }
    __syncthreads();
    float mx = redA[0];

    float e = __expf(val - mx) * m;
    float wsm = e;
    #pragma unroll
    for (int off = 16; off; off >>= 1) wsm += __shfl_xor_sync(0xffffffffu, wsm, off);
    if (lane == 0) redB[wid] = wsm;
    __syncthreads();
    if (wid == 0) {
        float t = redB[lane];
        #pragma unroll
        for (int off = 16; off; off >>= 1) t += __shfl_xor_sync(0xffffffffu, t, off);
        if (lane == 0) redB[0] = t;
    }
    __syncthreads();
    float sum = redB[0];
    float inv = (sum == 0.0f) ? 1.0f : (1.0f / sum);
    alphas[b*SS + s] = e * inv;
    if (s == 0) { g_M[b] = mx; g_invZ[b] = inv; }
}

// ---------------------------------------------------------------------------
// out[b][o] = sum_t g_part[t][o] * exp(m_t - M_b) / Z_b   (16 tiles per batch)
// ---------------------------------------------------------------------------
__global__ __launch_bounds__(256)
void k_reduce(float* __restrict__ out)
{
    __shared__ float sc[16];
    const int b = blockIdx.x;
    const int o = threadIdx.x;
    if (o < 16) sc[o] = __expf(g_mt[b*16 + o] - g_M[b]) * g_invZ[b];
    __syncthreads();
    float s = 0.0f;
    #pragma unroll
    for (int t = 0; t < 16; t++)
        s += g_part[((size_t)(b*16 + t)) * OO + o] * sc[t];
    out[b*OO + o] = s;
}

// ---------------------------------------------------------------------------
extern "C" void kernel_launch(void* const* d_in, const int* in_sizes, int n_in,
                              void* d_out, int out_size)
{
    const float* x    = (const float*)d_in[0];   // [B,S,D]
    const float* mask = (const float*)d_in[1];   // [B,S]
    const float* W    = (const float*)d_in[2];   // [D,A]
    const float* bv   = (const float*)d_in[3];   // [A]
    const float* u    = (const float*)d_in[4];   // [A]
    const float* Uo   = (const float*)d_in[5];   // [A,O]

    float* out    = (float*)d_out;               // [B,O]
    float* alphas = out + BB * OO;               // [B,S]
    float* betas  = alphas + BB * SS;            // [B,S,O]

    cudaFuncSetAttribute(k_fused, cudaFuncAttributeMaxDynamicSharedMemorySize, SMEM_BYTES);

    dim3 tg(8, 8, 2), tb(32, 8);
    k_prep<<<tg, tb>>>(W, Uo);
    k_fused<<<NROWS / TILE_R, 256, SMEM_BYTES>>>(x, mask, bv, u, betas);
    k_alphas<<<BB, 1024>>>(mask, alphas);
    k_reduce<<<BB, 256>>>(out);
}